// round 4
// baseline (speedup 1.0000x reference)
#include <cuda_runtime.h>
#include <math.h>
#include <float.h>

#define B_ROWS 4096
#define C_COLS 128
#define WARPS_PER_BLOCK 32
#define NBLOCKS (B_ROWS / WARPS_PER_BLOCK)   // 128 -> single wave on 148 SMs

#define FP_SCALE 4194304.0f      // 2^22 fixed-point scale
#define FP_INV   (1.0f / 4194304.0f)

// Deterministic integer accumulators (fixed-point) + completion counter.
__device__ long long          g_bce;
__device__ long long          g_wl;
__device__ unsigned long long g_pos;
__device__ unsigned int       g_count;

__device__ __forceinline__ float softplus_fast(float t) {
    return fmaxf(t, 0.0f) + __logf(1.0f + __expf(-fabsf(t)));
}

__device__ __forceinline__ float warp_sum(float v) {
    #pragma unroll
    for (int o = 16; o > 0; o >>= 1)
        v += __shfl_xor_sync(0xFFFFFFFFu, v, o);
    return v;
}

__device__ __forceinline__ float warp_max(float v) {
    #pragma unroll
    for (int o = 16; o > 0; o >>= 1)
        v = fmaxf(v, __shfl_xor_sync(0xFFFFFFFFu, v, o));
    return v;
}

__global__ void __launch_bounds__(32 * WARPS_PER_BLOCK)
fused_kernel(const float* __restrict__ x, const int* __restrict__ tgt,
             float* __restrict__ out) {
    const int warp = threadIdx.y;
    const int lane = threadIdx.x;
    const int row  = blockIdx.x * WARPS_PER_BLOCK + warp;

    // one LDG.128 per operand per warp
    const float4 xv = ((const float4*)(x   + (size_t)row * C_COLS))[lane];
    const int4   lv = ((const int4*)  (tgt + (size_t)row * C_COLS))[lane];
    float xs[4] = {xv.x, xv.y, xv.z, xv.w};
    int   ls[4] = {lv.x, lv.y, lv.z, lv.w};

    // ---- BCE + negative-class max + positive count ----
    float bce  = 0.0f;
    float mneg = -FLT_MAX;
    int   npos = 0;
    #pragma unroll
    for (int k = 0; k < 4; k++) {
        float t = ls[k] ? -xs[k] : xs[k];
        bce += softplus_fast(t);
        if (!ls[k]) mneg = fmaxf(mneg, xs[k]);
        npos += __popc(__ballot_sync(0xFFFFFFFFu, ls[k] != 0));
    }
    mneg = warp_max(mneg);

    // ---- Z = sum over negatives of exp(x_i - M) ----
    float z = 0.0f;
    #pragma unroll
    for (int k = 0; k < 4; k++)
        if (!ls[k]) z += __expf(xs[k] - mneg);
    z = warp_sum(z);

    // ---- per-positive lse_j = m + log(e^-m + Z*e^{M-x_j-m}), m=max(0,M-x_j) ----
    float wl = 0.0f;
    #pragma unroll
    for (int k = 0; k < 4; k++) {
        if (ls[k]) {
            float d = mneg - xs[k];
            float m = fmaxf(0.0f, d);
            wl += m + __logf(__expf(-m) + z * __expf(d - m));
        }
    }

    bce = warp_sum(bce);
    wl  = warp_sum(wl);

    // ---- block reduction: warp leaders -> smem -> warp 0 ----
    __shared__ float s_b[WARPS_PER_BLOCK];
    __shared__ float s_w[WARPS_PER_BLOCK];
    __shared__ int   s_p[WARPS_PER_BLOCK];
    if (lane == 0) { s_b[warp] = bce; s_w[warp] = wl; s_p[warp] = npos; }
    __syncthreads();

    if (warp == 0) {
        float b = warp_sum(s_b[lane]);
        float w = warp_sum(s_w[lane]);
        int   p = s_p[lane];
        #pragma unroll
        for (int o = 16; o > 0; o >>= 1)
            p += __shfl_xor_sync(0xFFFFFFFFu, p, o);

        if (lane == 0) {
            // Deterministic: integer adds are order-independent.
            atomicAdd((unsigned long long*)&g_bce,
                      (unsigned long long)(long long)__float2ll_rn(b * FP_SCALE));
            atomicAdd((unsigned long long*)&g_wl,
                      (unsigned long long)(long long)__float2ll_rn(w * FP_SCALE));
            atomicAdd(&g_pos, (unsigned long long)p);
            __threadfence();
            unsigned int v = atomicAdd(&g_count, 1u);
            if (v == (unsigned)(gridDim.x - 1)) {
                __threadfence();   // acquire: see all other blocks' atomics
                long long          tb = *(volatile long long*)&g_bce;
                long long          tw = *(volatile long long*)&g_wl;
                unsigned long long tp = *(volatile unsigned long long*)&g_pos;
                float bce_mean = ((float)tb * FP_INV) / (float)(B_ROWS * C_COLS);
                float wlsep    = ((float)tw * FP_INV) / (float)tp;
                out[0] = bce_mean + wlsep;
                // reset for next graph replay
                g_bce = 0; g_wl = 0; g_pos = 0; g_count = 0;
            }
        }
    }
}

extern "C" void kernel_launch(void* const* d_in, const int* in_sizes, int n_in,
                              void* d_out, int out_size) {
    (void)in_sizes; (void)n_in; (void)out_size;
    const float* x   = (const float*)d_in[0];
    const int*   tgt = (const int*)d_in[1];
    float*       out = (float*)d_out;

    dim3 blk(32, WARPS_PER_BLOCK);
    fused_kernel<<<NBLOCKS, blk>>>(x, tgt, out);
}

// round 5
// speedup vs baseline: 1.0295x; 1.0295x over previous
#include <cuda_runtime.h>
#include <math.h>
#include <float.h>

#define B_ROWS 4096
#define C_COLS 128
#define WARPS_PER_BLOCK 16          // 512 threads; each warp handles 2 rows
#define ROWS_PER_BLOCK  (WARPS_PER_BLOCK * 2)
#define NBLOCKS (B_ROWS / ROWS_PER_BLOCK)   // 128 -> single wave on 148 SMs

#define FP_SCALE 4194304.0f      // 2^22 fixed-point scale
#define FP_INV   (1.0f / 4194304.0f)

// Deterministic integer accumulators (fixed-point) + completion counter.
__device__ long long          g_bce;
__device__ long long          g_wl;
__device__ unsigned long long g_pos;
__device__ unsigned int       g_count;

__device__ __forceinline__ float warp_sum(float v) {
    #pragma unroll
    for (int o = 16; o > 0; o >>= 1)
        v += __shfl_xor_sync(0xFFFFFFFFu, v, o);
    return v;
}

__global__ void __launch_bounds__(32 * WARPS_PER_BLOCK)
fused_kernel(const float* __restrict__ x, const int* __restrict__ tgt,
             float* __restrict__ out) {
    const int warp = threadIdx.y;
    const int lane = threadIdx.x;
    const int row0 = (blockIdx.x * WARPS_PER_BLOCK + warp) * 2;
    const int row1 = row0 + 1;

    // 4 independent LDG.128 per thread -> good MLP
    const float4 xa = ((const float4*)(x   + (size_t)row0 * C_COLS))[lane];
    const float4 xb = ((const float4*)(x   + (size_t)row1 * C_COLS))[lane];
    const int4   la = ((const int4*)  (tgt + (size_t)row0 * C_COLS))[lane];
    const int4   lb = ((const int4*)  (tgt + (size_t)row1 * C_COLS))[lane];

    float xs0[4] = {xa.x, xa.y, xa.z, xa.w};
    float xs1[4] = {xb.x, xb.y, xb.z, xb.w};
    int   ls0[4] = {la.x, la.y, la.z, la.w};
    int   ls1[4] = {lb.x, lb.y, lb.z, lb.w};

    // ---- E = exp(x) once per element (the only per-element MUFU) ----
    float E0[4], E1[4];
    #pragma unroll
    for (int k = 0; k < 4; k++) { E0[k] = __expf(xs0[k]); E1[k] = __expf(xs1[k]); }

    // ---- fused pass: bce product, per-row Z partials, sum of positive x ----
    float pb  = 1.0f;      // prod (1 + E) over all 8 elems -> one log
    float z0  = 0.0f, z1 = 0.0f;
    float sxp = 0.0f;      // sum of x over positives (both rows)
    int   npos = 0;
    #pragma unroll
    for (int k = 0; k < 4; k++) {
        pb *= (1.0f + E0[k]) * (1.0f + E1[k]);
        if (ls0[k]) sxp += xs0[k]; else z0 += E0[k];
        if (ls1[k]) sxp += xs1[k]; else z1 += E1[k];
        npos += __popc(__ballot_sync(0xFFFFFFFFu, ls0[k] != 0));
        npos += __popc(__ballot_sync(0xFFFFFFFFu, ls1[k] != 0));
    }
    z0 = warp_sum(z0);     // row0 Z = sum over negatives of exp(x_i)
    z1 = warp_sum(z1);     // (independent chains -> interleaved by scheduler)

    // ---- lse product: prod over positives of (E_j + Z_row) -> one log ----
    // lse_j = log(1 + Z*exp(-x_j)) = log(E_j + Z) - x_j
    float pl = 1.0f;
    #pragma unroll
    for (int k = 0; k < 4; k++) {
        if (ls0[k]) pl *= (E0[k] + z0);
        if (ls1[k]) pl *= (E1[k] + z1);
    }

    // per-thread contributions (2 logs total per 8 elements)
    float bce_t = __logf(pb) - sxp;
    float wl_t  = __logf(pl) - sxp;

    bce_t = warp_sum(bce_t);
    wl_t  = warp_sum(wl_t);

    // ---- block reduction over 16 warps ----
    __shared__ float s_b[WARPS_PER_BLOCK];
    __shared__ float s_w[WARPS_PER_BLOCK];
    __shared__ int   s_p[WARPS_PER_BLOCK];
    if (lane == 0) { s_b[warp] = bce_t; s_w[warp] = wl_t; s_p[warp] = npos; }
    __syncthreads();

    if (warp == 0 && lane < WARPS_PER_BLOCK) {
        float b = s_b[lane];
        float w = s_w[lane];
        int   p = s_p[lane];
        #pragma unroll
        for (int o = WARPS_PER_BLOCK / 2; o > 0; o >>= 1) {
            b += __shfl_xor_sync(0xFFFFu, b, o);
            w += __shfl_xor_sync(0xFFFFu, w, o);
            p += __shfl_xor_sync(0xFFFFu, p, o);
        }
        if (lane == 0) {
            // Deterministic: integer adds are order-independent.
            atomicAdd((unsigned long long*)&g_bce,
                      (unsigned long long)(long long)__float2ll_rn(b * FP_SCALE));
            atomicAdd((unsigned long long*)&g_wl,
                      (unsigned long long)(long long)__float2ll_rn(w * FP_SCALE));
            atomicAdd(&g_pos, (unsigned long long)p);
            __threadfence();
            unsigned int v = atomicAdd(&g_count, 1u);
            if (v == (unsigned)(gridDim.x - 1)) {
                __threadfence();   // acquire: see all other blocks' atomics
                long long          tb = *(volatile long long*)&g_bce;
                long long          tw = *(volatile long long*)&g_wl;
                unsigned long long tp = *(volatile unsigned long long*)&g_pos;
                float bce_mean = ((float)tb * FP_INV) / (float)(B_ROWS * C_COLS);
                float wlsep    = ((float)tw * FP_INV) / (float)tp;
                out[0] = bce_mean + wlsep;
                // reset for next graph replay
                g_bce = 0; g_wl = 0; g_pos = 0; g_count = 0;
            }
        }
    }
}

extern "C" void kernel_launch(void* const* d_in, const int* in_sizes, int n_in,
                              void* d_out, int out_size) {
    (void)in_sizes; (void)n_in; (void)out_size;
    const float* x   = (const float*)d_in[0];
    const int*   tgt = (const int*)d_in[1];
    float*       out = (float*)d_out;

    dim3 blk(32, WARPS_PER_BLOCK);
    fused_kernel<<<NBLOCKS, blk>>>(x, tgt, out);
}